// round 6
// baseline (speedup 1.0000x reference)
#include <cuda_runtime.h>
#include <math.h>

#define NN    100000
#define NE    3200000
#define NFEAT 512
#define NH    16
#define NC    7
#define NB_NODES 391   /* ceil(NN/256) */
#define NB_EDGES 12500 /* ceil(NE/256) */

// ---------------- device scratch (static, no allocs) ----------------
__device__ int   g_is64;
__device__ int   g_deg[NN];
__device__ float g_dinv[NN];
__device__ int   g_cur[NN];          // exclusive prefix, then cursor -> row end
__device__ int   g_bsum[NB_NODES];
__device__ int2  g_edge[NE];         // {src, norm-as-float-bits} in CSR-by-dst order
__device__ float g_hl1[NN * 16];     // x @ W1
__device__ float g_hl2[NN * 8];      // relu(agg1+b1) @ W2, padded stride 8

// ---------------- dtype detection (int64 vs int32 edge_index) ----------------
// If the buffer is int64 little-endian with values < 2^31, every odd 32-bit
// word is 0. Sample odd words from BOTH the src half and the dst half.
__global__ void k_detect(const int* __restrict__ e32) {
    __shared__ int any;
    int t = threadIdx.x;
    if (t == 0) any = 0;
    __syncthreads();
    int acc = 0;
#pragma unroll
    for (int j = 0; j < 16; j++) {
        acc |= e32[2 * (t + 256 * j) + 1];            // src half (int64 view)
        acc |= e32[2 * (NE + t + 256 * j) + 1];       // dst half (int64 view)
    }
    if (acc) atomicOr(&any, 1);
    __syncthreads();
    if (t == 0) g_is64 = (any == 0) ? 1 : 0;
}

__global__ void k_zero() {
    int i = blockIdx.x * 256 + threadIdx.x;
    if (i < NN) g_deg[i] = 0;
}

__global__ void k_hist(const int* __restrict__ e32) {
    int e = blockIdx.x * 256 + threadIdx.x;
    if (e >= NE) return;
    int is64 = g_is64;
    int d = is64 ? e32[2 * (NE + e)] : e32[NE + e];
    atomicAdd(&g_deg[d], 1);
}

__global__ void k_dinv() {
    int i = blockIdx.x * 256 + threadIdx.x;
    if (i < NN) g_dinv[i] = rsqrtf((float)g_deg[i] + 1.0f);
}

// ---------------- exclusive scan of g_deg into g_cur ----------------
__global__ void k_scanA() {
    __shared__ int sh[256];
    int t = threadIdx.x, i = blockIdx.x * 256 + t;
    sh[t] = (i < NN) ? g_deg[i] : 0;
    __syncthreads();
    for (int off = 128; off; off >>= 1) {
        if (t < off) sh[t] += sh[t + off];
        __syncthreads();
    }
    if (t == 0) g_bsum[blockIdx.x] = sh[0];
}

__global__ void k_scanB() {
    __shared__ int sh[512];
    int t = threadIdx.x;
    int v = (t < NB_NODES) ? g_bsum[t] : 0;
    sh[t] = v;
    __syncthreads();
    for (int off = 1; off < 512; off <<= 1) {
        int u = (t >= off) ? sh[t - off] : 0;
        __syncthreads();
        sh[t] += u;
        __syncthreads();
    }
    if (t < NB_NODES) g_bsum[t] = sh[t] - v;  // exclusive
}

__global__ void k_scanC() {
    __shared__ int sh[256];
    int t = threadIdx.x, i = blockIdx.x * 256 + t;
    int d = (i < NN) ? g_deg[i] : 0;
    sh[t] = d;
    __syncthreads();
    for (int off = 1; off < 256; off <<= 1) {
        int u = (t >= off) ? sh[t - off] : 0;
        __syncthreads();
        sh[t] += u;
        __syncthreads();
    }
    if (i < NN) g_cur[i] = sh[t] - d + g_bsum[blockIdx.x];
}

__global__ void k_scatter(const int* __restrict__ e32) {
    int e = blockIdx.x * 256 + threadIdx.x;
    if (e >= NE) return;
    int is64 = g_is64;
    int s = is64 ? e32[2 * e] : e32[e];
    int d = is64 ? e32[2 * (NE + e)] : e32[NE + e];
    int pos = atomicAdd(&g_cur[d], 1);
    float w = g_dinv[s] * g_dinv[d];
    g_edge[pos] = make_int2(s, __float_as_int(w));
}

// ---------------- GEMM1: g_hl1 = x @ W1  (no bias) ----------------
// block = 256 threads = 8 warps; each warp owns 32 nodes; x staged in smem
// transposed with pad-33 (conflict-free), W chunk staged + uniform broadcast.
__global__ void k_gemm1(const float* __restrict__ x, const float* __restrict__ W1) {
    __shared__ float xs[8][32][33];
    __shared__ float Wc[512];  // 32 k-rows x 16 cols
    int t = threadIdx.x;
    int w = t >> 5, lane = t & 31;
    int nb = blockIdx.x * 256 + w * 32;
    int node = nb + lane;
    float a[16];
#pragma unroll
    for (int c = 0; c < 16; c++) a[c] = 0.f;

    for (int kc = 0; kc < NFEAT; kc += 32) {
        __syncthreads();
        Wc[t]       = W1[kc * 16 + t];
        Wc[t + 256] = W1[kc * 16 + 256 + t];
#pragma unroll 8
        for (int n = 0; n < 32; n++) {
            int nn = nb + n;
            xs[w][n][lane] = (nn < NN) ? x[(size_t)nn * NFEAT + kc + lane] : 0.f;
        }
        __syncthreads();
#pragma unroll
        for (int k = 0; k < 32; k++) {
            float xv = xs[w][lane][k];
            const float4* wp = reinterpret_cast<const float4*>(Wc + k * 16);
            float4 w0 = wp[0], w1 = wp[1], w2 = wp[2], w3 = wp[3];
            a[0]  = fmaf(xv, w0.x, a[0]);  a[1]  = fmaf(xv, w0.y, a[1]);
            a[2]  = fmaf(xv, w0.z, a[2]);  a[3]  = fmaf(xv, w0.w, a[3]);
            a[4]  = fmaf(xv, w1.x, a[4]);  a[5]  = fmaf(xv, w1.y, a[5]);
            a[6]  = fmaf(xv, w1.z, a[6]);  a[7]  = fmaf(xv, w1.w, a[7]);
            a[8]  = fmaf(xv, w2.x, a[8]);  a[9]  = fmaf(xv, w2.y, a[9]);
            a[10] = fmaf(xv, w2.z, a[10]); a[11] = fmaf(xv, w2.w, a[11]);
            a[12] = fmaf(xv, w3.x, a[12]); a[13] = fmaf(xv, w3.y, a[13]);
            a[14] = fmaf(xv, w3.z, a[14]); a[15] = fmaf(xv, w3.w, a[15]);
        }
    }
    if (node < NN) {
        float4* o = reinterpret_cast<float4*>(g_hl1 + (size_t)node * 16);
        o[0] = make_float4(a[0], a[1], a[2], a[3]);
        o[1] = make_float4(a[4], a[5], a[6], a[7]);
        o[2] = make_float4(a[8], a[9], a[10], a[11]);
        o[3] = make_float4(a[12], a[13], a[14], a[15]);
    }
}

// ---------------- agg1 + bias + relu + (@W2) fused ----------------
// 2-edge unroll with independent accumulator banks -> 2 gathers in flight.
__global__ void k_agg1(const float* __restrict__ b1, const float* __restrict__ W2) {
    __shared__ float sb1[16];
    __shared__ float sW2[112];
    if (threadIdx.x < 16)  sb1[threadIdx.x] = b1[threadIdx.x];
    if (threadIdx.x < 112) sW2[threadIdx.x] = W2[threadIdx.x];
    __syncthreads();
    int i = blockIdx.x * 256 + threadIdx.x;
    if (i >= NN) return;

    int end = g_cur[i];
    int beg = end - g_deg[i];

    float a[16], b[16];
#pragma unroll
    for (int c = 0; c < 16; c++) { a[c] = 0.f; b[c] = 0.f; }

    int e = beg;
    for (; e + 1 < end; e += 2) {
        int2 e0 = g_edge[e];
        int2 e1 = g_edge[e + 1];
        const float4* p0 = reinterpret_cast<const float4*>(g_hl1 + (size_t)e0.x * 16);
        const float4* p1 = reinterpret_cast<const float4*>(g_hl1 + (size_t)e1.x * 16);
        float w0 = __int_as_float(e0.y);
        float w1 = __int_as_float(e1.y);
#pragma unroll
        for (int j = 0; j < 4; j++) {
            float4 h0 = p0[j];
            float4 h1 = p1[j];
            a[4 * j + 0] = fmaf(w0, h0.x, a[4 * j + 0]);
            a[4 * j + 1] = fmaf(w0, h0.y, a[4 * j + 1]);
            a[4 * j + 2] = fmaf(w0, h0.z, a[4 * j + 2]);
            a[4 * j + 3] = fmaf(w0, h0.w, a[4 * j + 3]);
            b[4 * j + 0] = fmaf(w1, h1.x, b[4 * j + 0]);
            b[4 * j + 1] = fmaf(w1, h1.y, b[4 * j + 1]);
            b[4 * j + 2] = fmaf(w1, h1.z, b[4 * j + 2]);
            b[4 * j + 3] = fmaf(w1, h1.w, b[4 * j + 3]);
        }
    }
    if (e < end) {
        int2 e0 = g_edge[e];
        const float4* p0 = reinterpret_cast<const float4*>(g_hl1 + (size_t)e0.x * 16);
        float w0 = __int_as_float(e0.y);
#pragma unroll
        for (int j = 0; j < 4; j++) {
            float4 h0 = p0[j];
            a[4 * j + 0] = fmaf(w0, h0.x, a[4 * j + 0]);
            a[4 * j + 1] = fmaf(w0, h0.y, a[4 * j + 1]);
            a[4 * j + 2] = fmaf(w0, h0.z, a[4 * j + 2]);
            a[4 * j + 3] = fmaf(w0, h0.w, a[4 * j + 3]);
        }
    }
    // self loop
    {
        float di = g_dinv[i];
        float ws = di * di;
        const float4* hp = reinterpret_cast<const float4*>(g_hl1 + (size_t)i * 16);
#pragma unroll
        for (int j = 0; j < 4; j++) {
            float4 h = hp[j];
            a[4 * j + 0] = fmaf(ws, h.x, a[4 * j + 0]);
            a[4 * j + 1] = fmaf(ws, h.y, a[4 * j + 1]);
            a[4 * j + 2] = fmaf(ws, h.z, a[4 * j + 2]);
            a[4 * j + 3] = fmaf(ws, h.w, a[4 * j + 3]);
        }
    }
    // bias + relu + x@W2 (16x7)
    float o[7];
#pragma unroll
    for (int c2 = 0; c2 < 7; c2++) o[c2] = 0.f;
#pragma unroll
    for (int c = 0; c < 16; c++) {
        float r = fmaxf((a[c] + b[c]) + sb1[c], 0.f);
#pragma unroll
        for (int c2 = 0; c2 < 7; c2++) o[c2] = fmaf(r, sW2[c * 7 + c2], o[c2]);
    }
    float4* dst = reinterpret_cast<float4*>(g_hl2 + (size_t)i * 8);
    dst[0] = make_float4(o[0], o[1], o[2], o[3]);
    dst[1] = make_float4(o[4], o[5], o[6], 0.f);
}

// ---------------- agg2 + bias + log_softmax ----------------
__global__ void k_agg2(const float* __restrict__ b2, float* __restrict__ out) {
    __shared__ float sb2[7];
    if (threadIdx.x < 7) sb2[threadIdx.x] = b2[threadIdx.x];
    __syncthreads();
    int i = blockIdx.x * 256 + threadIdx.x;
    if (i >= NN) return;

    int end = g_cur[i];
    int beg = end - g_deg[i];

    float a[8], b[8];
#pragma unroll
    for (int c = 0; c < 8; c++) { a[c] = 0.f; b[c] = 0.f; }

    int e = beg;
    for (; e + 1 < end; e += 2) {
        int2 e0 = g_edge[e];
        int2 e1 = g_edge[e + 1];
        const float4* p0 = reinterpret_cast<const float4*>(g_hl2 + (size_t)e0.x * 8);
        const float4* p1 = reinterpret_cast<const float4*>(g_hl2 + (size_t)e1.x * 8);
        float w0 = __int_as_float(e0.y);
        float w1 = __int_as_float(e1.y);
        float4 h00 = p0[0], h01 = p0[1];
        float4 h10 = p1[0], h11 = p1[1];
        a[0] = fmaf(w0, h00.x, a[0]); a[1] = fmaf(w0, h00.y, a[1]);
        a[2] = fmaf(w0, h00.z, a[2]); a[3] = fmaf(w0, h00.w, a[3]);
        a[4] = fmaf(w0, h01.x, a[4]); a[5] = fmaf(w0, h01.y, a[5]);
        a[6] = fmaf(w0, h01.z, a[6]);
        b[0] = fmaf(w1, h10.x, b[0]); b[1] = fmaf(w1, h10.y, b[1]);
        b[2] = fmaf(w1, h10.z, b[2]); b[3] = fmaf(w1, h10.w, b[3]);
        b[4] = fmaf(w1, h11.x, b[4]); b[5] = fmaf(w1, h11.y, b[5]);
        b[6] = fmaf(w1, h11.z, b[6]);
    }
    if (e < end) {
        int2 e0 = g_edge[e];
        const float4* p0 = reinterpret_cast<const float4*>(g_hl2 + (size_t)e0.x * 8);
        float w0 = __int_as_float(e0.y);
        float4 h0 = p0[0], h1 = p0[1];
        a[0] = fmaf(w0, h0.x, a[0]); a[1] = fmaf(w0, h0.y, a[1]);
        a[2] = fmaf(w0, h0.z, a[2]); a[3] = fmaf(w0, h0.w, a[3]);
        a[4] = fmaf(w0, h1.x, a[4]); a[5] = fmaf(w0, h1.y, a[5]);
        a[6] = fmaf(w0, h1.z, a[6]);
    }
    {
        float di = g_dinv[i];
        float ws = di * di;
        const float4* hp = reinterpret_cast<const float4*>(g_hl2 + (size_t)i * 8);
        float4 h0 = hp[0], h1 = hp[1];
        a[0] = fmaf(ws, h0.x, a[0]); a[1] = fmaf(ws, h0.y, a[1]);
        a[2] = fmaf(ws, h0.z, a[2]); a[3] = fmaf(ws, h0.w, a[3]);
        a[4] = fmaf(ws, h1.x, a[4]); a[5] = fmaf(ws, h1.y, a[5]);
        a[6] = fmaf(ws, h1.z, a[6]);
    }
    float v[7];
#pragma unroll
    for (int c = 0; c < 7; c++) v[c] = (a[c] + b[c]) + sb2[c];
    float m = v[0];
#pragma unroll
    for (int c = 1; c < 7; c++) m = fmaxf(m, v[c]);
    float ssum = 0.f;
#pragma unroll
    for (int c = 0; c < 7; c++) ssum += expf(v[c] - m);
    float ls = logf(ssum);
    float* op = out + (size_t)i * 7;
#pragma unroll
    for (int c = 0; c < 7; c++) op[c] = v[c] - m - ls;
}

// ---------------- launch ----------------
extern "C" void kernel_launch(void* const* d_in, const int* in_sizes, int n_in,
                              void* d_out, int out_size) {
    const float* x   = (const float*)d_in[0];
    const int*   e32 = (const int*)d_in[1];  // int32 or int64 (detected on device)
    const float* W1  = (const float*)d_in[2];
    const float* b1  = (const float*)d_in[3];
    const float* W2  = (const float*)d_in[4];
    const float* b2  = (const float*)d_in[5];
    float* out = (float*)d_out;

    k_detect<<<1, 256>>>(e32);
    k_zero<<<NB_NODES, 256>>>();
    k_hist<<<NB_EDGES, 256>>>(e32);
    k_dinv<<<NB_NODES, 256>>>();
    k_scanA<<<NB_NODES, 256>>>();
    k_scanB<<<1, 512>>>();
    k_scanC<<<NB_NODES, 256>>>();
    k_scatter<<<NB_EDGES, 256>>>(e32);
    k_gemm1<<<NB_NODES, 256>>>(x, W1);
    k_agg1<<<NB_NODES, 256>>>(b1, W2);
    k_agg2<<<NB_NODES, 256>>>(b2, out);
}

// round 7
// speedup vs baseline: 1.1188x; 1.1188x over previous
#include <cuda_runtime.h>
#include <math.h>

#define NN    100000
#define NE    3200000
#define NFEAT 512
#define NH    16
#define NC    7
#define NB_NODES 391    /* ceil(NN/256) */
#define NB_EPAIR 6250   /* ceil(NE/2/256) */

// ---------------- device scratch (static, no allocs) ----------------
__device__ int   g_is64;
__device__ int   g_deg[NN];
__device__ float g_dinv[NN];
__device__ int   g_cur[NN];          // exclusive prefix, then cursor -> row end
__device__ int   g_bsum[NB_NODES];
__device__ int2  g_edge[NE];         // {src, norm-as-float-bits} in CSR-by-dst order
__device__ float g_hl1[NN * 16];     // x @ W1
__device__ float g_hl2[NN * 8];      // relu(agg1+b1) @ W2, padded stride 8

// ---------------- init: zero deg + dtype detection fused ----------------
// If the buffer is int64 little-endian with values < 2^31, every odd 32-bit
// word is 0. Sample odd words from BOTH the src half and the dst half.
__global__ void k_init(const int* __restrict__ e32) {
    int i = blockIdx.x * 256 + threadIdx.x;
    if (i < NN) g_deg[i] = 0;
    if (blockIdx.x == 0) {
        __shared__ int any;
        int t = threadIdx.x;
        if (t == 0) any = 0;
        __syncthreads();
        int acc = 0;
#pragma unroll
        for (int j = 0; j < 16; j++) {
            acc |= e32[2 * (t + 256 * j) + 1];       // src half (int64 view)
            acc |= e32[2 * (NE + t + 256 * j) + 1];  // dst half (int64 view)
        }
        if (acc) atomicOr(&any, 1);
        __syncthreads();
        if (t == 0) g_is64 = (any == 0) ? 1 : 0;
    }
}

// ---------------- histogram over dst, 2 edges/thread, vectorized ----------------
__global__ void k_hist(const int* __restrict__ e32) {
    int t = blockIdx.x * 256 + threadIdx.x;  // pair index
    if (2 * t >= NE) return;
    if (g_is64) {
        int4 v = *reinterpret_cast<const int4*>(e32 + 2 * NE + 4 * t);
        atomicAdd(&g_deg[v.x], 1);
        atomicAdd(&g_deg[v.z], 1);
    } else {
        int2 v = *reinterpret_cast<const int2*>(e32 + NE + 2 * t);
        atomicAdd(&g_deg[v.x], 1);
        atomicAdd(&g_deg[v.y], 1);
    }
}

// ---------------- scan stage A (block sums) + dinv fused ----------------
__global__ void k_scanA() {
    __shared__ int sh[256];
    int t = threadIdx.x, i = blockIdx.x * 256 + t;
    int d = (i < NN) ? g_deg[i] : 0;
    if (i < NN) g_dinv[i] = rsqrtf((float)d + 1.0f);
    sh[t] = d;
    __syncthreads();
    for (int off = 128; off; off >>= 1) {
        if (t < off) sh[t] += sh[t + off];
        __syncthreads();
    }
    if (t == 0) g_bsum[blockIdx.x] = sh[0];
}

__global__ void k_scanB() {
    __shared__ int sh[512];
    int t = threadIdx.x;
    int v = (t < NB_NODES) ? g_bsum[t] : 0;
    sh[t] = v;
    __syncthreads();
    for (int off = 1; off < 512; off <<= 1) {
        int u = (t >= off) ? sh[t - off] : 0;
        __syncthreads();
        sh[t] += u;
        __syncthreads();
    }
    if (t < NB_NODES) g_bsum[t] = sh[t] - v;  // exclusive
}

__global__ void k_scanC() {
    __shared__ int sh[256];
    int t = threadIdx.x, i = blockIdx.x * 256 + t;
    int d = (i < NN) ? g_deg[i] : 0;
    sh[t] = d;
    __syncthreads();
    for (int off = 1; off < 256; off <<= 1) {
        int u = (t >= off) ? sh[t - off] : 0;
        __syncthreads();
        sh[t] += u;
        __syncthreads();
    }
    if (i < NN) g_cur[i] = sh[t] - d + g_bsum[blockIdx.x];
}

// ---------------- scatter into CSR, 2 edges/thread, vectorized ----------------
__global__ void k_scatter(const int* __restrict__ e32) {
    int t = blockIdx.x * 256 + threadIdx.x;  // pair index
    if (2 * t >= NE) return;
    int s0, s1, d0, d1;
    if (g_is64) {
        int4 sv = *reinterpret_cast<const int4*>(e32 + 4 * t);
        int4 dv = *reinterpret_cast<const int4*>(e32 + 2 * NE + 4 * t);
        s0 = sv.x; s1 = sv.z; d0 = dv.x; d1 = dv.z;
    } else {
        int2 sv = *reinterpret_cast<const int2*>(e32 + 2 * t);
        int2 dv = *reinterpret_cast<const int2*>(e32 + NE + 2 * t);
        s0 = sv.x; s1 = sv.y; d0 = dv.x; d1 = dv.y;
    }
    float w0 = g_dinv[s0] * g_dinv[d0];
    float w1 = g_dinv[s1] * g_dinv[d1];
    int p0 = atomicAdd(&g_cur[d0], 1);
    g_edge[p0] = make_int2(s0, __float_as_int(w0));
    int p1 = atomicAdd(&g_cur[d1], 1);
    g_edge[p1] = make_int2(s1, __float_as_int(w1));
}

// ---------------- GEMM1: g_hl1 = x @ W1  (no bias) ----------------
// block = 256 threads = 8 warps; each warp owns 32 nodes; x staged in smem
// transposed with pad-33 (conflict-free), W chunk staged + uniform broadcast.
__global__ void k_gemm1(const float* __restrict__ x, const float* __restrict__ W1) {
    __shared__ float xs[8][32][33];
    __shared__ float Wc[512];  // 32 k-rows x 16 cols
    int t = threadIdx.x;
    int w = t >> 5, lane = t & 31;
    int nb = blockIdx.x * 256 + w * 32;
    int node = nb + lane;
    float a[16];
#pragma unroll
    for (int c = 0; c < 16; c++) a[c] = 0.f;

    for (int kc = 0; kc < NFEAT; kc += 32) {
        __syncthreads();
        Wc[t]       = W1[kc * 16 + t];
        Wc[t + 256] = W1[kc * 16 + 256 + t];
#pragma unroll 8
        for (int n = 0; n < 32; n++) {
            int nn = nb + n;
            xs[w][n][lane] = (nn < NN) ? x[(size_t)nn * NFEAT + kc + lane] : 0.f;
        }
        __syncthreads();
#pragma unroll
        for (int k = 0; k < 32; k++) {
            float xv = xs[w][lane][k];
            const float4* wp = reinterpret_cast<const float4*>(Wc + k * 16);
            float4 w0 = wp[0], w1 = wp[1], w2 = wp[2], w3 = wp[3];
            a[0]  = fmaf(xv, w0.x, a[0]);  a[1]  = fmaf(xv, w0.y, a[1]);
            a[2]  = fmaf(xv, w0.z, a[2]);  a[3]  = fmaf(xv, w0.w, a[3]);
            a[4]  = fmaf(xv, w1.x, a[4]);  a[5]  = fmaf(xv, w1.y, a[5]);
            a[6]  = fmaf(xv, w1.z, a[6]);  a[7]  = fmaf(xv, w1.w, a[7]);
            a[8]  = fmaf(xv, w2.x, a[8]);  a[9]  = fmaf(xv, w2.y, a[9]);
            a[10] = fmaf(xv, w2.z, a[10]); a[11] = fmaf(xv, w2.w, a[11]);
            a[12] = fmaf(xv, w3.x, a[12]); a[13] = fmaf(xv, w3.y, a[13]);
            a[14] = fmaf(xv, w3.z, a[14]); a[15] = fmaf(xv, w3.w, a[15]);
        }
    }
    if (node < NN) {
        float4* o = reinterpret_cast<float4*>(g_hl1 + (size_t)node * 16);
        o[0] = make_float4(a[0], a[1], a[2], a[3]);
        o[1] = make_float4(a[4], a[5], a[6], a[7]);
        o[2] = make_float4(a[8], a[9], a[10], a[11]);
        o[3] = make_float4(a[12], a[13], a[14], a[15]);
    }
}

// ---------------- agg1 + bias + relu + (@W2) fused ----------------
// 2-edge unroll with independent accumulator banks -> 2 gathers in flight.
__global__ void k_agg1(const float* __restrict__ b1, const float* __restrict__ W2) {
    __shared__ float sb1[16];
    __shared__ float sW2[112];
    if (threadIdx.x < 16)  sb1[threadIdx.x] = b1[threadIdx.x];
    if (threadIdx.x < 112) sW2[threadIdx.x] = W2[threadIdx.x];
    __syncthreads();
    int i = blockIdx.x * 256 + threadIdx.x;
    if (i >= NN) return;

    int end = g_cur[i];
    int beg = end - g_deg[i];

    float a[16], b[16];
#pragma unroll
    for (int c = 0; c < 16; c++) { a[c] = 0.f; b[c] = 0.f; }

    int e = beg;
    for (; e + 1 < end; e += 2) {
        int2 e0 = g_edge[e];
        int2 e1 = g_edge[e + 1];
        const float4* p0 = reinterpret_cast<const float4*>(g_hl1 + (size_t)e0.x * 16);
        const float4* p1 = reinterpret_cast<const float4*>(g_hl1 + (size_t)e1.x * 16);
        float w0 = __int_as_float(e0.y);
        float w1 = __int_as_float(e1.y);
#pragma unroll
        for (int j = 0; j < 4; j++) {
            float4 h0 = p0[j];
            float4 h1 = p1[j];
            a[4 * j + 0] = fmaf(w0, h0.x, a[4 * j + 0]);
            a[4 * j + 1] = fmaf(w0, h0.y, a[4 * j + 1]);
            a[4 * j + 2] = fmaf(w0, h0.z, a[4 * j + 2]);
            a[4 * j + 3] = fmaf(w0, h0.w, a[4 * j + 3]);
            b[4 * j + 0] = fmaf(w1, h1.x, b[4 * j + 0]);
            b[4 * j + 1] = fmaf(w1, h1.y, b[4 * j + 1]);
            b[4 * j + 2] = fmaf(w1, h1.z, b[4 * j + 2]);
            b[4 * j + 3] = fmaf(w1, h1.w, b[4 * j + 3]);
        }
    }
    if (e < end) {
        int2 e0 = g_edge[e];
        const float4* p0 = reinterpret_cast<const float4*>(g_hl1 + (size_t)e0.x * 16);
        float w0 = __int_as_float(e0.y);
#pragma unroll
        for (int j = 0; j < 4; j++) {
            float4 h0 = p0[j];
            a[4 * j + 0] = fmaf(w0, h0.x, a[4 * j + 0]);
            a[4 * j + 1] = fmaf(w0, h0.y, a[4 * j + 1]);
            a[4 * j + 2] = fmaf(w0, h0.z, a[4 * j + 2]);
            a[4 * j + 3] = fmaf(w0, h0.w, a[4 * j + 3]);
        }
    }
    // self loop
    {
        float di = g_dinv[i];
        float ws = di * di;
        const float4* hp = reinterpret_cast<const float4*>(g_hl1 + (size_t)i * 16);
#pragma unroll
        for (int j = 0; j < 4; j++) {
            float4 h = hp[j];
            a[4 * j + 0] = fmaf(ws, h.x, a[4 * j + 0]);
            a[4 * j + 1] = fmaf(ws, h.y, a[4 * j + 1]);
            a[4 * j + 2] = fmaf(ws, h.z, a[4 * j + 2]);
            a[4 * j + 3] = fmaf(ws, h.w, a[4 * j + 3]);
        }
    }
    // bias + relu + x@W2 (16x7)
    float o[7];
#pragma unroll
    for (int c2 = 0; c2 < 7; c2++) o[c2] = 0.f;
#pragma unroll
    for (int c = 0; c < 16; c++) {
        float r = fmaxf((a[c] + b[c]) + sb1[c], 0.f);
#pragma unroll
        for (int c2 = 0; c2 < 7; c2++) o[c2] = fmaf(r, sW2[c * 7 + c2], o[c2]);
    }
    float4* dst = reinterpret_cast<float4*>(g_hl2 + (size_t)i * 8);
    dst[0] = make_float4(o[0], o[1], o[2], o[3]);
    dst[1] = make_float4(o[4], o[5], o[6], 0.f);
}

// ---------------- agg2 + bias + log_softmax ----------------
__global__ void k_agg2(const float* __restrict__ b2, float* __restrict__ out) {
    __shared__ float sb2[7];
    if (threadIdx.x < 7) sb2[threadIdx.x] = b2[threadIdx.x];
    __syncthreads();
    int i = blockIdx.x * 256 + threadIdx.x;
    if (i >= NN) return;

    int end = g_cur[i];
    int beg = end - g_deg[i];

    float a[8], b[8];
#pragma unroll
    for (int c = 0; c < 8; c++) { a[c] = 0.f; b[c] = 0.f; }

    int e = beg;
    for (; e + 1 < end; e += 2) {
        int2 e0 = g_edge[e];
        int2 e1 = g_edge[e + 1];
        const float4* p0 = reinterpret_cast<const float4*>(g_hl2 + (size_t)e0.x * 8);
        const float4* p1 = reinterpret_cast<const float4*>(g_hl2 + (size_t)e1.x * 8);
        float w0 = __int_as_float(e0.y);
        float w1 = __int_as_float(e1.y);
        float4 h00 = p0[0], h01 = p0[1];
        float4 h10 = p1[0], h11 = p1[1];
        a[0] = fmaf(w0, h00.x, a[0]); a[1] = fmaf(w0, h00.y, a[1]);
        a[2] = fmaf(w0, h00.z, a[2]); a[3] = fmaf(w0, h00.w, a[3]);
        a[4] = fmaf(w0, h01.x, a[4]); a[5] = fmaf(w0, h01.y, a[5]);
        a[6] = fmaf(w0, h01.z, a[6]);
        b[0] = fmaf(w1, h10.x, b[0]); b[1] = fmaf(w1, h10.y, b[1]);
        b[2] = fmaf(w1, h10.z, b[2]); b[3] = fmaf(w1, h10.w, b[3]);
        b[4] = fmaf(w1, h11.x, b[4]); b[5] = fmaf(w1, h11.y, b[5]);
        b[6] = fmaf(w1, h11.z, b[6]);
    }
    if (e < end) {
        int2 e0 = g_edge[e];
        const float4* p0 = reinterpret_cast<const float4*>(g_hl2 + (size_t)e0.x * 8);
        float w0 = __int_as_float(e0.y);
        float4 h0 = p0[0], h1 = p0[1];
        a[0] = fmaf(w0, h0.x, a[0]); a[1] = fmaf(w0, h0.y, a[1]);
        a[2] = fmaf(w0, h0.z, a[2]); a[3] = fmaf(w0, h0.w, a[3]);
        a[4] = fmaf(w0, h1.x, a[4]); a[5] = fmaf(w0, h1.y, a[5]);
        a[6] = fmaf(w0, h1.z, a[6]);
    }
    {
        float di = g_dinv[i];
        float ws = di * di;
        const float4* hp = reinterpret_cast<const float4*>(g_hl2 + (size_t)i * 8);
        float4 h0 = hp[0], h1 = hp[1];
        a[0] = fmaf(ws, h0.x, a[0]); a[1] = fmaf(ws, h0.y, a[1]);
        a[2] = fmaf(ws, h0.z, a[2]); a[3] = fmaf(ws, h0.w, a[3]);
        a[4] = fmaf(ws, h1.x, a[4]); a[5] = fmaf(ws, h1.y, a[5]);
        a[6] = fmaf(ws, h1.z, a[6]);
    }
    float v[7];
#pragma unroll
    for (int c = 0; c < 7; c++) v[c] = (a[c] + b[c]) + sb2[c];
    float m = v[0];
#pragma unroll
    for (int c = 1; c < 7; c++) m = fmaxf(m, v[c]);
    float ssum = 0.f;
#pragma unroll
    for (int c = 0; c < 7; c++) ssum += expf(v[c] - m);
    float ls = logf(ssum);
    float* op = out + (size_t)i * 7;
#pragma unroll
    for (int c = 0; c < 7; c++) op[c] = v[c] - m - ls;
}

// ---------------- launch: fork gemm1 onto side stream, join before agg1 ----
extern "C" void kernel_launch(void* const* d_in, const int* in_sizes, int n_in,
                              void* d_out, int out_size) {
    const float* x   = (const float*)d_in[0];
    const int*   e32 = (const int*)d_in[1];  // int32 or int64 (detected on device)
    const float* W1  = (const float*)d_in[2];
    const float* b1  = (const float*)d_in[3];
    const float* W2  = (const float*)d_in[4];
    const float* b2  = (const float*)d_in[5];
    float* out = (float*)d_out;

    // Host-side resources created once (no device memory involved).
    static cudaStream_t s2 = nullptr;
    static cudaEvent_t evFork = nullptr, evJoin = nullptr;
    if (s2 == nullptr) {
        cudaStreamCreateWithFlags(&s2, cudaStreamNonBlocking);
        cudaEventCreateWithFlags(&evFork, cudaEventDisableTiming);
        cudaEventCreateWithFlags(&evJoin, cudaEventDisableTiming);
    }

    // Fork: gemm1 (FMA-bound, depends only on x/W1) runs concurrently with
    // the CSR-build chain (memory/atomic-bound, depends only on edge_index).
    cudaEventRecord(evFork, 0);
    cudaStreamWaitEvent(s2, evFork, 0);
    k_gemm1<<<NB_NODES, 256, 0, s2>>>(x, W1);
    cudaEventRecord(evJoin, s2);

    // CSR-build chain on the main (captured) stream.
    k_init<<<NB_NODES, 256>>>(e32);
    k_hist<<<NB_EPAIR, 256>>>(e32);
    k_scanA<<<NB_NODES, 256>>>();
    k_scanB<<<1, 512>>>();
    k_scanC<<<NB_NODES, 256>>>();
    k_scatter<<<NB_EPAIR, 256>>>(e32);

    // Join: agg1 needs both gemm1 (g_hl1) and the CSR (g_edge/g_cur/g_deg).
    cudaStreamWaitEvent(0, evJoin, 0);
    k_agg1<<<NB_NODES, 256>>>(b1, W2);
    k_agg2<<<NB_NODES, 256>>>(b2, out);
}

// round 8
// speedup vs baseline: 1.3129x; 1.1735x over previous
#include <cuda_runtime.h>
#include <math.h>

#define NN    100000
#define NE    3200000
#define NFEAT 512
#define NH    16
#define NC    7
#define NB_NODES 391    /* ceil(NN/256) */
#define NB_EPAIR 6250   /* ceil(NE/2/256) */
#define NB_AGG1  1563   /* ceil(NN/64)  : 8 nodes/warp, 8 warps */
#define NB_AGG2  782    /* ceil(NN/128) : 16 nodes/warp, 8 warps */

// ---------------- device scratch (static, no allocs) ----------------
__device__ int   g_is64;
__device__ int   g_deg[NN];
__device__ float g_dinv[NN];
__device__ int   g_cur[NN];          // exclusive prefix, then cursor -> row end
__device__ int   g_bsum[NB_NODES];
__device__ int2  g_edge[NE];         // {src, norm-as-float-bits} in CSR-by-dst order
__device__ float g_hl1[NN * 16];     // x @ W1
__device__ float g_hl2[NN * 8];      // relu(agg1+b1) @ W2, padded stride 8

// ---------------- init: zero deg + dtype detection fused ----------------
__global__ void k_init(const int* __restrict__ e32) {
    int i = blockIdx.x * 256 + threadIdx.x;
    if (i < NN) g_deg[i] = 0;
    if (blockIdx.x == 0) {
        __shared__ int any;
        int t = threadIdx.x;
        if (t == 0) any = 0;
        __syncthreads();
        int acc = 0;
#pragma unroll
        for (int j = 0; j < 16; j++) {
            acc |= e32[2 * (t + 256 * j) + 1];       // src half (int64 view)
            acc |= e32[2 * (NE + t + 256 * j) + 1];  // dst half (int64 view)
        }
        if (acc) atomicOr(&any, 1);
        __syncthreads();
        if (t == 0) g_is64 = (any == 0) ? 1 : 0;
    }
}

// ---------------- histogram over dst, 2 edges/thread, vectorized ----------------
__global__ void k_hist(const int* __restrict__ e32) {
    int t = blockIdx.x * 256 + threadIdx.x;  // pair index
    if (2 * t >= NE) return;
    if (g_is64) {
        int4 v = *reinterpret_cast<const int4*>(e32 + 2 * NE + 4 * t);
        atomicAdd(&g_deg[v.x], 1);
        atomicAdd(&g_deg[v.z], 1);
    } else {
        int2 v = *reinterpret_cast<const int2*>(e32 + NE + 2 * t);
        atomicAdd(&g_deg[v.x], 1);
        atomicAdd(&g_deg[v.y], 1);
    }
}

// ---------------- scan stage A (block sums) + dinv fused ----------------
__global__ void k_scanA() {
    __shared__ int sh[256];
    int t = threadIdx.x, i = blockIdx.x * 256 + t;
    int d = (i < NN) ? g_deg[i] : 0;
    if (i < NN) g_dinv[i] = rsqrtf((float)d + 1.0f);
    sh[t] = d;
    __syncthreads();
    for (int off = 128; off; off >>= 1) {
        if (t < off) sh[t] += sh[t + off];
        __syncthreads();
    }
    if (t == 0) g_bsum[blockIdx.x] = sh[0];
}

__global__ void k_scanB() {
    __shared__ int sh[512];
    int t = threadIdx.x;
    int v = (t < NB_NODES) ? g_bsum[t] : 0;
    sh[t] = v;
    __syncthreads();
    for (int off = 1; off < 512; off <<= 1) {
        int u = (t >= off) ? sh[t - off] : 0;
        __syncthreads();
        sh[t] += u;
        __syncthreads();
    }
    if (t < NB_NODES) g_bsum[t] = sh[t] - v;  // exclusive
}

__global__ void k_scanC() {
    __shared__ int sh[256];
    int t = threadIdx.x, i = blockIdx.x * 256 + t;
    int d = (i < NN) ? g_deg[i] : 0;
    sh[t] = d;
    __syncthreads();
    for (int off = 1; off < 256; off <<= 1) {
        int u = (t >= off) ? sh[t - off] : 0;
        __syncthreads();
        sh[t] += u;
        __syncthreads();
    }
    if (i < NN) g_cur[i] = sh[t] - d + g_bsum[blockIdx.x];
}

// ---------------- scatter into CSR, 2 edges/thread, vectorized ----------------
__global__ void k_scatter(const int* __restrict__ e32) {
    int t = blockIdx.x * 256 + threadIdx.x;  // pair index
    if (2 * t >= NE) return;
    int s0, s1, d0, d1;
    if (g_is64) {
        int4 sv = *reinterpret_cast<const int4*>(e32 + 4 * t);
        int4 dv = *reinterpret_cast<const int4*>(e32 + 2 * NE + 4 * t);
        s0 = sv.x; s1 = sv.z; d0 = dv.x; d1 = dv.z;
    } else {
        int2 sv = *reinterpret_cast<const int2*>(e32 + 2 * t);
        int2 dv = *reinterpret_cast<const int2*>(e32 + NE + 2 * t);
        s0 = sv.x; s1 = sv.y; d0 = dv.x; d1 = dv.y;
    }
    float w0 = g_dinv[s0] * g_dinv[d0];
    float w1 = g_dinv[s1] * g_dinv[d1];
    int p0 = atomicAdd(&g_cur[d0], 1);
    g_edge[p0] = make_int2(s0, __float_as_int(w0));
    int p1 = atomicAdd(&g_cur[d1], 1);
    g_edge[p1] = make_int2(s1, __float_as_int(w1));
}

// ---------------- GEMM1: g_hl1 = x @ W1, f32x2 packed FMA ----------------
__global__ void k_gemm1(const float* __restrict__ x, const float* __restrict__ W1) {
    __shared__ float xs[8][32][33];
    __shared__ float Wc[512];  // 32 k-rows x 16 cols
    int t = threadIdx.x;
    int w = t >> 5, lane = t & 31;
    int nb = blockIdx.x * 256 + w * 32;
    int node = nb + lane;
    unsigned long long acc[8];  // 8 x f32x2 = 16 fp32 accumulators
#pragma unroll
    for (int j = 0; j < 8; j++) acc[j] = 0ull;

    for (int kc = 0; kc < NFEAT; kc += 32) {
        __syncthreads();
        Wc[t]       = W1[kc * 16 + t];
        Wc[t + 256] = W1[kc * 16 + 256 + t];
#pragma unroll 8
        for (int n = 0; n < 32; n++) {
            int nn = nb + n;
            xs[w][n][lane] = (nn < NN) ? x[(size_t)nn * NFEAT + kc + lane] : 0.f;
        }
        __syncthreads();
#pragma unroll
        for (int k = 0; k < 32; k++) {
            float xv = xs[w][lane][k];
            unsigned long long xv2;
            asm("mov.b64 %0, {%1, %1};" : "=l"(xv2) : "f"(xv));
            const ulonglong2* wp = reinterpret_cast<const ulonglong2*>(Wc + k * 16);
            ulonglong2 p0 = wp[0], p1 = wp[1], p2 = wp[2], p3 = wp[3];
            asm("fma.rn.f32x2 %0, %1, %2, %0;" : "+l"(acc[0]) : "l"(xv2), "l"(p0.x));
            asm("fma.rn.f32x2 %0, %1, %2, %0;" : "+l"(acc[1]) : "l"(xv2), "l"(p0.y));
            asm("fma.rn.f32x2 %0, %1, %2, %0;" : "+l"(acc[2]) : "l"(xv2), "l"(p1.x));
            asm("fma.rn.f32x2 %0, %1, %2, %0;" : "+l"(acc[3]) : "l"(xv2), "l"(p1.y));
            asm("fma.rn.f32x2 %0, %1, %2, %0;" : "+l"(acc[4]) : "l"(xv2), "l"(p2.x));
            asm("fma.rn.f32x2 %0, %1, %2, %0;" : "+l"(acc[5]) : "l"(xv2), "l"(p2.y));
            asm("fma.rn.f32x2 %0, %1, %2, %0;" : "+l"(acc[6]) : "l"(xv2), "l"(p3.x));
            asm("fma.rn.f32x2 %0, %1, %2, %0;" : "+l"(acc[7]) : "l"(xv2), "l"(p3.y));
        }
    }
    if (node < NN) {
        float lo[8], hi[8];
#pragma unroll
        for (int j = 0; j < 8; j++)
            asm("mov.b64 {%0, %1}, %2;" : "=f"(lo[j]), "=f"(hi[j]) : "l"(acc[j]));
        float4* o = reinterpret_cast<float4*>(g_hl1 + (size_t)node * 16);
        o[0] = make_float4(lo[0], hi[0], lo[1], hi[1]);
        o[1] = make_float4(lo[2], hi[2], lo[3], hi[3]);
        o[2] = make_float4(lo[4], hi[4], lo[5], hi[5]);
        o[3] = make_float4(lo[6], hi[6], lo[7], hi[7]);
    }
}

// ---------------- agg1: 4 lanes per node (lane owns 4 features) ----------------
// Gather LDG.128 per warp touches 8 lines (one 64B row per 4-lane group)
// instead of 32 -> 4x fewer L1tex wavefronts.
__global__ void k_agg1(const float* __restrict__ b1, const float* __restrict__ W2) {
    __shared__ float sb1[16];
    __shared__ float sW2[112];
    if (threadIdx.x < 16)  sb1[threadIdx.x] = b1[threadIdx.x];
    if (threadIdx.x < 112) sW2[threadIdx.x] = W2[threadIdx.x];
    __syncthreads();
    int t = threadIdx.x;
    int warp = t >> 5, lane = t & 31;
    int g = lane >> 2, r = lane & 3;
    int i = blockIdx.x * 64 + warp * 8 + g;
    bool active = (i < NN);
    int ii = active ? i : (NN - 1);
    int end = g_cur[ii];
    int deg = active ? g_deg[ii] : 0;
    int beg = end - deg;
    int md = (int)__reduce_max_sync(0xffffffffu, (unsigned)deg);

    float a0 = 0.f, a1 = 0.f, a2 = 0.f, a3 = 0.f;

    for (int ch = 0; ch < md; ch += 8) {
        int i0 = beg + ch + r;
        int i1 = i0 + 4;
        if (i0 >= NE) i0 = NE - 1;
        if (i1 >= NE) i1 = NE - 1;
        int2 ea = g_edge[i0];
        int2 eb = g_edge[i1];
#pragma unroll
        for (int sub = 0; sub < 8; sub++) {
            int src = (sub < 4) ? ea.x : eb.x;
            int wb  = (sub < 4) ? ea.y : eb.y;
            int sl = (g << 2) + (sub & 3);
            int s  = __shfl_sync(0xffffffffu, src, sl);
            int wv = __shfl_sync(0xffffffffu, wb, sl);
            if (ch + sub < deg) {
                float wgt = __int_as_float(wv);
                float4 h = *reinterpret_cast<const float4*>(g_hl1 + (size_t)s * 16 + 4 * r);
                a0 = fmaf(wgt, h.x, a0);
                a1 = fmaf(wgt, h.y, a1);
                a2 = fmaf(wgt, h.z, a2);
                a3 = fmaf(wgt, h.w, a3);
            }
        }
    }
    // self loop
    if (active) {
        float di = g_dinv[i];
        float ws = di * di;
        float4 h = *reinterpret_cast<const float4*>(g_hl1 + (size_t)i * 16 + 4 * r);
        a0 = fmaf(ws, h.x, a0);
        a1 = fmaf(ws, h.y, a1);
        a2 = fmaf(ws, h.z, a2);
        a3 = fmaf(ws, h.w, a3);
    }
    // bias + relu on this lane's 4 features, partial 16x7 product
    float r0 = fmaxf(a0 + sb1[4 * r + 0], 0.f);
    float r1 = fmaxf(a1 + sb1[4 * r + 1], 0.f);
    float r2 = fmaxf(a2 + sb1[4 * r + 2], 0.f);
    float r3 = fmaxf(a3 + sb1[4 * r + 3], 0.f);
    float o[7];
#pragma unroll
    for (int c2 = 0; c2 < 7; c2++) {
        float v = r0 * sW2[(4 * r + 0) * 7 + c2];
        v = fmaf(r1, sW2[(4 * r + 1) * 7 + c2], v);
        v = fmaf(r2, sW2[(4 * r + 2) * 7 + c2], v);
        v = fmaf(r3, sW2[(4 * r + 3) * 7 + c2], v);
        o[c2] = v;
    }
    // reduce across the 4-lane group
#pragma unroll
    for (int c2 = 0; c2 < 7; c2++) {
        o[c2] += __shfl_xor_sync(0xffffffffu, o[c2], 1);
        o[c2] += __shfl_xor_sync(0xffffffffu, o[c2], 2);
    }
    if (active) {
        if (r == 0)
            *reinterpret_cast<float4*>(g_hl2 + (size_t)i * 8) =
                make_float4(o[0], o[1], o[2], o[3]);
        if (r == 1)
            *reinterpret_cast<float4*>(g_hl2 + (size_t)i * 8 + 4) =
                make_float4(o[4], o[5], o[6], 0.f);
    }
}

// ---------------- agg2: 2 lanes per node + log_softmax ----------------
__global__ void k_agg2(const float* __restrict__ b2, float* __restrict__ out) {
    __shared__ float sb2[8];
    if (threadIdx.x < 8) sb2[threadIdx.x] = (threadIdx.x < 7) ? b2[threadIdx.x] : 0.f;
    __syncthreads();
    int t = threadIdx.x;
    int warp = t >> 5, lane = t & 31;
    int g = lane >> 1, r = lane & 1;
    int i = blockIdx.x * 128 + warp * 16 + g;
    bool active = (i < NN);
    int ii = active ? i : (NN - 1);
    int end = g_cur[ii];
    int deg = active ? g_deg[ii] : 0;
    int beg = end - deg;
    int md = (int)__reduce_max_sync(0xffffffffu, (unsigned)deg);

    float a0 = 0.f, a1 = 0.f, a2 = 0.f, a3 = 0.f;

    for (int ch = 0; ch < md; ch += 4) {
        int i0 = beg + ch + r;
        int i1 = i0 + 2;
        if (i0 >= NE) i0 = NE - 1;
        if (i1 >= NE) i1 = NE - 1;
        int2 ea = g_edge[i0];
        int2 eb = g_edge[i1];
#pragma unroll
        for (int sub = 0; sub < 4; sub++) {
            int src = (sub & 2) ? eb.x : ea.x;
            int wb  = (sub & 2) ? eb.y : ea.y;
            int sl = (g << 1) + (sub & 1);
            int s  = __shfl_sync(0xffffffffu, src, sl);
            int wv = __shfl_sync(0xffffffffu, wb, sl);
            if (ch + sub < deg) {
                float wgt = __int_as_float(wv);
                float4 h = *reinterpret_cast<const float4*>(g_hl2 + (size_t)s * 8 + 4 * r);
                a0 = fmaf(wgt, h.x, a0);
                a1 = fmaf(wgt, h.y, a1);
                a2 = fmaf(wgt, h.z, a2);
                a3 = fmaf(wgt, h.w, a3);
            }
        }
    }
    if (active) {
        float di = g_dinv[i];
        float ws = di * di;
        float4 h = *reinterpret_cast<const float4*>(g_hl2 + (size_t)i * 8 + 4 * r);
        a0 = fmaf(ws, h.x, a0);
        a1 = fmaf(ws, h.y, a1);
        a2 = fmaf(ws, h.z, a2);
        a3 = fmaf(ws, h.w, a3);
    }
    // lane r holds features 4r..4r+3 (feature 7 is padding, contributes 0)
    float m0 = a0 + sb2[4 * r + 0];
    float m1 = a1 + sb2[4 * r + 1];
    float m2 = a2 + sb2[4 * r + 2];
    float m3 = a3 + sb2[4 * r + 3];
    float t0 = __shfl_xor_sync(0xffffffffu, m0, 1);
    float t1 = __shfl_xor_sync(0xffffffffu, m1, 1);
    float t2 = __shfl_xor_sync(0xffffffffu, m2, 1);
    float t3 = __shfl_xor_sync(0xffffffffu, m3, 1);
    float v0, v1, v2, v3, v4, v5, v6;
    if (r == 0) { v0 = m0; v1 = m1; v2 = m2; v3 = m3; v4 = t0; v5 = t1; v6 = t2; }
    else        { v0 = t0; v1 = t1; v2 = t2; v3 = t3; v4 = m0; v5 = m1; v6 = m2; }
    float mx = fmaxf(fmaxf(fmaxf(v0, v1), fmaxf(v2, v3)), fmaxf(fmaxf(v4, v5), v6));
    float ssum = expf(v0 - mx) + expf(v1 - mx) + expf(v2 - mx) + expf(v3 - mx)
               + expf(v4 - mx) + expf(v5 - mx) + expf(v6 - mx);
    float ls = mx + logf(ssum);
    if (active) {
        float* op = out + (size_t)i * 7;
        if (r == 0) {
            op[0] = v0 - ls; op[1] = v1 - ls; op[2] = v2 - ls; op[3] = v3 - ls;
        } else {
            op[4] = v4 - ls; op[5] = v5 - ls; op[6] = v6 - ls;
        }
    }
}

// ---------------- launch: fork gemm1 onto side stream, join before agg1 ----
extern "C" void kernel_launch(void* const* d_in, const int* in_sizes, int n_in,
                              void* d_out, int out_size) {
    const float* x   = (const float*)d_in[0];
    const int*   e32 = (const int*)d_in[1];  // int32 or int64 (detected on device)
    const float* W1  = (const float*)d_in[2];
    const float* b1  = (const float*)d_in[3];
    const float* W2  = (const float*)d_in[4];
    const float* b2  = (const float*)d_in[5];
    float* out = (float*)d_out;

    static cudaStream_t s2 = nullptr;
    static cudaEvent_t evFork = nullptr, evJoin = nullptr;
    if (s2 == nullptr) {
        cudaStreamCreateWithFlags(&s2, cudaStreamNonBlocking);
        cudaEventCreateWithFlags(&evFork, cudaEventDisableTiming);
        cudaEventCreateWithFlags(&evJoin, cudaEventDisableTiming);
    }

    cudaEventRecord(evFork, 0);
    cudaStreamWaitEvent(s2, evFork, 0);
    k_gemm1<<<NB_NODES, 256, 0, s2>>>(x, W1);
    cudaEventRecord(evJoin, s2);

    k_init<<<NB_NODES, 256>>>(e32);
    k_hist<<<NB_EPAIR, 256>>>(e32);
    k_scanA<<<NB_NODES, 256>>>();
    k_scanB<<<1, 512>>>();
    k_scanC<<<NB_NODES, 256>>>();
    k_scatter<<<NB_EPAIR, 256>>>(e32);

    cudaStreamWaitEvent(0, evJoin, 0);
    k_agg1<<<NB_AGG1, 256>>>(b1, W2);
    k_agg2<<<NB_AGG2, 256>>>(b2, out);
}

// round 9
// speedup vs baseline: 1.4015x; 1.0675x over previous
#include <cuda_runtime.h>
#include <math.h>

#define NN    100000
#define NE    3200000
#define NFEAT 512
#define NH    16
#define NC    7
#define NB_NODES 391    /* ceil(NN/256) */
#define NB_EPAIR 6250   /* ceil(NE/2/256) */
#define NB_EQUAD 3125   /* ceil(NE/4/256) */
#define NB_AGG1  1563   /* ceil(NN/64)  : 8 nodes/warp, 8 warps */
#define NB_AGG2  782    /* ceil(NN/128) : 16 nodes/warp, 8 warps */

// ---------------- device scratch (static, no allocs) ----------------
__device__ int   g_is64;
__device__ int   g_deg[NN];
__device__ float g_dinv[NN];
__device__ int   g_cur[NN];          // exclusive prefix, then cursor -> row end
__device__ int   g_bsum[NB_NODES];
__device__ int   g_esrc[NE];         // src index only, CSR-by-dst order
__device__ float g_hl1[NN * 16];     // x @ W1, then scaled by dinv (h')
__device__ float g_hl2[NN * 8];      // dinv * (relu(.)@W2), padded stride 8

// ---------------- init: zero deg + dtype detection fused ----------------
__global__ void k_init(const int* __restrict__ e32) {
    int i = blockIdx.x * 256 + threadIdx.x;
    if (i < NN) g_deg[i] = 0;
    if (blockIdx.x == 0) {
        __shared__ int any;
        int t = threadIdx.x;
        if (t == 0) any = 0;
        __syncthreads();
        int acc = 0;
#pragma unroll
        for (int j = 0; j < 16; j++) {
            acc |= e32[2 * (t + 256 * j) + 1];       // src half (int64 view)
            acc |= e32[2 * (NE + t + 256 * j) + 1];  // dst half (int64 view)
        }
        if (acc) atomicOr(&any, 1);
        __syncthreads();
        if (t == 0) g_is64 = (any == 0) ? 1 : 0;
    }
}

// ---------------- histogram over dst, 4 edges/thread ----------------
__global__ void k_hist(const int* __restrict__ e32) {
    int t = blockIdx.x * 256 + threadIdx.x;  // quad index
    if (4 * t >= NE) return;
    if (g_is64) {
        int4 a = *reinterpret_cast<const int4*>(e32 + 2 * NE + 8 * t);
        int4 b = *reinterpret_cast<const int4*>(e32 + 2 * NE + 8 * t + 4);
        atomicAdd(&g_deg[a.x], 1);
        atomicAdd(&g_deg[a.z], 1);
        atomicAdd(&g_deg[b.x], 1);
        atomicAdd(&g_deg[b.z], 1);
    } else {
        int4 v = *reinterpret_cast<const int4*>(e32 + NE + 4 * t);
        atomicAdd(&g_deg[v.x], 1);
        atomicAdd(&g_deg[v.y], 1);
        atomicAdd(&g_deg[v.z], 1);
        atomicAdd(&g_deg[v.w], 1);
    }
}

// ---------------- scan stage A (block sums) + dinv fused ----------------
__global__ void k_scanA() {
    __shared__ int sh[256];
    int t = threadIdx.x, i = blockIdx.x * 256 + t;
    int d = (i < NN) ? g_deg[i] : 0;
    if (i < NN) g_dinv[i] = rsqrtf((float)d + 1.0f);
    sh[t] = d;
    __syncthreads();
    for (int off = 128; off; off >>= 1) {
        if (t < off) sh[t] += sh[t + off];
        __syncthreads();
    }
    if (t == 0) g_bsum[blockIdx.x] = sh[0];
}

__global__ void k_scanB() {
    __shared__ int sh[512];
    int t = threadIdx.x;
    int v = (t < NB_NODES) ? g_bsum[t] : 0;
    sh[t] = v;
    __syncthreads();
    for (int off = 1; off < 512; off <<= 1) {
        int u = (t >= off) ? sh[t - off] : 0;
        __syncthreads();
        sh[t] += u;
        __syncthreads();
    }
    if (t < NB_NODES) g_bsum[t] = sh[t] - v;  // exclusive
}

__global__ void k_scanC() {
    __shared__ int sh[256];
    int t = threadIdx.x, i = blockIdx.x * 256 + t;
    int d = (i < NN) ? g_deg[i] : 0;
    sh[t] = d;
    __syncthreads();
    for (int off = 1; off < 256; off <<= 1) {
        int u = (t >= off) ? sh[t - off] : 0;
        __syncthreads();
        sh[t] += u;
        __syncthreads();
    }
    if (i < NN) g_cur[i] = sh[t] - d + g_bsum[blockIdx.x];
}

// ---------------- scatter into CSR (src only), 2 edges/thread ----------------
__global__ void k_scatter(const int* __restrict__ e32) {
    int t = blockIdx.x * 256 + threadIdx.x;  // pair index
    if (2 * t >= NE) return;
    int s0, s1, d0, d1;
    if (g_is64) {
        int4 sv = *reinterpret_cast<const int4*>(e32 + 4 * t);
        int4 dv = *reinterpret_cast<const int4*>(e32 + 2 * NE + 4 * t);
        s0 = sv.x; s1 = sv.z; d0 = dv.x; d1 = dv.z;
    } else {
        int2 sv = *reinterpret_cast<const int2*>(e32 + 2 * t);
        int2 dv = *reinterpret_cast<const int2*>(e32 + NE + 2 * t);
        s0 = sv.x; s1 = sv.y; d0 = dv.x; d1 = dv.y;
    }
    int p0 = atomicAdd(&g_cur[d0], 1);
    g_esrc[p0] = s0;
    int p1 = atomicAdd(&g_cur[d1], 1);
    g_esrc[p1] = s1;
}

// ---------------- GEMM1: g_hl1 = x @ W1, f32x2 packed FMA ----------------
__global__ void k_gemm1(const float* __restrict__ x, const float* __restrict__ W1) {
    __shared__ float xs[8][32][33];
    __shared__ float Wc[512];  // 32 k-rows x 16 cols
    int t = threadIdx.x;
    int w = t >> 5, lane = t & 31;
    int nb = blockIdx.x * 256 + w * 32;
    int node = nb + lane;
    unsigned long long acc[8];  // 8 x f32x2 = 16 fp32 accumulators
#pragma unroll
    for (int j = 0; j < 8; j++) acc[j] = 0ull;

    for (int kc = 0; kc < NFEAT; kc += 32) {
        __syncthreads();
        Wc[t]       = W1[kc * 16 + t];
        Wc[t + 256] = W1[kc * 16 + 256 + t];
#pragma unroll 8
        for (int n = 0; n < 32; n++) {
            int nn = nb + n;
            xs[w][n][lane] = (nn < NN) ? x[(size_t)nn * NFEAT + kc + lane] : 0.f;
        }
        __syncthreads();
#pragma unroll
        for (int k = 0; k < 32; k++) {
            float xv = xs[w][lane][k];
            unsigned long long xv2;
            asm("mov.b64 %0, {%1, %1};" : "=l"(xv2) : "f"(xv));
            const ulonglong2* wp = reinterpret_cast<const ulonglong2*>(Wc + k * 16);
            ulonglong2 p0 = wp[0], p1 = wp[1], p2 = wp[2], p3 = wp[3];
            asm("fma.rn.f32x2 %0, %1, %2, %0;" : "+l"(acc[0]) : "l"(xv2), "l"(p0.x));
            asm("fma.rn.f32x2 %0, %1, %2, %0;" : "+l"(acc[1]) : "l"(xv2), "l"(p0.y));
            asm("fma.rn.f32x2 %0, %1, %2, %0;" : "+l"(acc[2]) : "l"(xv2), "l"(p1.x));
            asm("fma.rn.f32x2 %0, %1, %2, %0;" : "+l"(acc[3]) : "l"(xv2), "l"(p1.y));
            asm("fma.rn.f32x2 %0, %1, %2, %0;" : "+l"(acc[4]) : "l"(xv2), "l"(p2.x));
            asm("fma.rn.f32x2 %0, %1, %2, %0;" : "+l"(acc[5]) : "l"(xv2), "l"(p2.y));
            asm("fma.rn.f32x2 %0, %1, %2, %0;" : "+l"(acc[6]) : "l"(xv2), "l"(p3.x));
            asm("fma.rn.f32x2 %0, %1, %2, %0;" : "+l"(acc[7]) : "l"(xv2), "l"(p3.y));
        }
    }
    if (node < NN) {
        float lo[8], hi[8];
#pragma unroll
        for (int j = 0; j < 8; j++)
            asm("mov.b64 {%0, %1}, %2;" : "=f"(lo[j]), "=f"(hi[j]) : "l"(acc[j]));
        float4* o = reinterpret_cast<float4*>(g_hl1 + (size_t)node * 16);
        o[0] = make_float4(lo[0], hi[0], lo[1], hi[1]);
        o[1] = make_float4(lo[2], hi[2], lo[3], hi[3]);
        o[2] = make_float4(lo[4], hi[4], lo[5], hi[5]);
        o[3] = make_float4(lo[6], hi[6], lo[7], hi[7]);
    }
}

// ---------------- scale: g_hl1 row i *= dinv[i]  (overlapped with scatter) ----
__global__ void k_scale() {
    int i = blockIdx.x * 256 + threadIdx.x;
    if (i >= NN) return;
    float di = g_dinv[i];
    float4* p = reinterpret_cast<float4*>(g_hl1 + (size_t)i * 16);
#pragma unroll
    for (int j = 0; j < 4; j++) {
        float4 v = p[j];
        v.x *= di; v.y *= di; v.z *= di; v.w *= di;
        p[j] = v;
    }
}

// ---------------- agg1: 4 lanes/node, unweighted adds of pre-scaled rows ----
__global__ void k_agg1(const float* __restrict__ b1, const float* __restrict__ W2) {
    __shared__ float sb1[16];
    __shared__ float sW2[112];
    if (threadIdx.x < 16)  sb1[threadIdx.x] = b1[threadIdx.x];
    if (threadIdx.x < 112) sW2[threadIdx.x] = W2[threadIdx.x];
    __syncthreads();
    int t = threadIdx.x;
    int warp = t >> 5, lane = t & 31;
    int g = lane >> 2, r = lane & 3;
    int i = blockIdx.x * 64 + warp * 8 + g;
    bool active = (i < NN);
    int ii = active ? i : (NN - 1);
    int end = g_cur[ii];
    int deg = active ? g_deg[ii] : 0;
    int beg = end - deg;
    int md = (int)__reduce_max_sync(0xffffffffu, (unsigned)deg);

    float a0 = 0.f, a1 = 0.f, a2 = 0.f, a3 = 0.f;

    for (int ch = 0; ch < md; ch += 8) {
        int i0 = beg + ch + r;
        int i1 = i0 + 4;
        if (i0 >= NE) i0 = NE - 1;
        if (i1 >= NE) i1 = NE - 1;
        int ea = g_esrc[i0];
        int eb = g_esrc[i1];
#pragma unroll
        for (int sub = 0; sub < 8; sub++) {
            int src = (sub < 4) ? ea : eb;
            int sl = (g << 2) + (sub & 3);
            int s  = __shfl_sync(0xffffffffu, src, sl);
            if (ch + sub < deg) {
                float4 h = *reinterpret_cast<const float4*>(g_hl1 + (size_t)s * 16 + 4 * r);
                a0 += h.x; a1 += h.y; a2 += h.z; a3 += h.w;
            }
        }
    }
    // self loop: + h'[i]
    float di = active ? g_dinv[i] : 1.f;
    if (active) {
        float4 h = *reinterpret_cast<const float4*>(g_hl1 + (size_t)i * 16 + 4 * r);
        a0 += h.x; a1 += h.y; a2 += h.z; a3 += h.w;
    }
    // agg = dinv_i * sum; then bias + relu + @W2, group-reduce
    float r0 = fmaxf(fmaf(di, a0, sb1[4 * r + 0]), 0.f);
    float r1 = fmaxf(fmaf(di, a1, sb1[4 * r + 1]), 0.f);
    float r2 = fmaxf(fmaf(di, a2, sb1[4 * r + 2]), 0.f);
    float r3 = fmaxf(fmaf(di, a3, sb1[4 * r + 3]), 0.f);
    float o[7];
#pragma unroll
    for (int c2 = 0; c2 < 7; c2++) {
        float v = r0 * sW2[(4 * r + 0) * 7 + c2];
        v = fmaf(r1, sW2[(4 * r + 1) * 7 + c2], v);
        v = fmaf(r2, sW2[(4 * r + 2) * 7 + c2], v);
        v = fmaf(r3, sW2[(4 * r + 3) * 7 + c2], v);
        o[c2] = v;
    }
#pragma unroll
    for (int c2 = 0; c2 < 7; c2++) {
        o[c2] += __shfl_xor_sync(0xffffffffu, o[c2], 1);
        o[c2] += __shfl_xor_sync(0xffffffffu, o[c2], 2);
    }
    // store pre-scaled layer-2 features: h2'[i] = dinv_i * (r @ W2)
    if (active) {
        if (r == 0)
            *reinterpret_cast<float4*>(g_hl2 + (size_t)i * 8) =
                make_float4(di * o[0], di * o[1], di * o[2], di * o[3]);
        if (r == 1)
            *reinterpret_cast<float4*>(g_hl2 + (size_t)i * 8 + 4) =
                make_float4(di * o[4], di * o[5], di * o[6], 0.f);
    }
}

// ---------------- agg2: 2 lanes/node + bias + log_softmax ----------------
__global__ void k_agg2(const float* __restrict__ b2, float* __restrict__ out) {
    __shared__ float sb2[8];
    if (threadIdx.x < 8) sb2[threadIdx.x] = (threadIdx.x < 7) ? b2[threadIdx.x] : 0.f;
    __syncthreads();
    int t = threadIdx.x;
    int warp = t >> 5, lane = t & 31;
    int g = lane >> 1, r = lane & 1;
    int i = blockIdx.x * 128 + warp * 16 + g;
    bool active = (i < NN);
    int ii = active ? i : (NN - 1);
    int end = g_cur[ii];
    int deg = active ? g_deg[ii] : 0;
    int beg = end - deg;
    int md = (int)__reduce_max_sync(0xffffffffu, (unsigned)deg);

    float a0 = 0.f, a1 = 0.f, a2 = 0.f, a3 = 0.f;

    for (int ch = 0; ch < md; ch += 4) {
        int i0 = beg + ch + r;
        int i1 = i0 + 2;
        if (i0 >= NE) i0 = NE - 1;
        if (i1 >= NE) i1 = NE - 1;
        int ea = g_esrc[i0];
        int eb = g_esrc[i1];
#pragma unroll
        for (int sub = 0; sub < 4; sub++) {
            int src = (sub & 2) ? eb : ea;
            int sl = (g << 1) + (sub & 1);
            int s  = __shfl_sync(0xffffffffu, src, sl);
            if (ch + sub < deg) {
                float4 h = *reinterpret_cast<const float4*>(g_hl2 + (size_t)s * 8 + 4 * r);
                a0 += h.x; a1 += h.y; a2 += h.z; a3 += h.w;
            }
        }
    }
    float di = active ? g_dinv[i] : 1.f;
    if (active) {
        float4 h = *reinterpret_cast<const float4*>(g_hl2 + (size_t)i * 8 + 4 * r);
        a0 += h.x; a1 += h.y; a2 += h.z; a3 += h.w;
    }
    // lane r holds features 4r..4r+3 (feature 7 is padding, contributes 0)
    float m0 = fmaf(di, a0, sb2[4 * r + 0]);
    float m1 = fmaf(di, a1, sb2[4 * r + 1]);
    float m2 = fmaf(di, a2, sb2[4 * r + 2]);
    float m3 = fmaf(di, a3, sb2[4 * r + 3]);
    float t0 = __shfl_xor_sync(0xffffffffu, m0, 1);
    float t1 = __shfl_xor_sync(0xffffffffu, m1, 1);
    float t2 = __shfl_xor_sync(0xffffffffu, m2, 1);
    float t3 = __shfl_xor_sync(0xffffffffu, m3, 1);
    float v0, v1, v2, v3, v4, v5, v6;
    if (r == 0) { v0 = m0; v1 = m1; v2 = m2; v3 = m3; v4 = t0; v5 = t1; v6 = t2; }
    else        { v0 = t0; v1 = t1; v2 = t2; v3 = t3; v4 = m0; v5 = m1; v6 = m2; }
    float mx = fmaxf(fmaxf(fmaxf(v0, v1), fmaxf(v2, v3)), fmaxf(fmaxf(v4, v5), v6));
    float ssum = expf(v0 - mx) + expf(v1 - mx) + expf(v2 - mx) + expf(v3 - mx)
               + expf(v4 - mx) + expf(v5 - mx) + expf(v6 - mx);
    float ls = mx + logf(ssum);
    if (active) {
        float* op = out + (size_t)i * 7;
        if (r == 0) {
            op[0] = v0 - ls; op[1] = v1 - ls; op[2] = v2 - ls; op[3] = v3 - ls;
        } else {
            op[4] = v4 - ls; op[5] = v5 - ls; op[6] = v6 - ls;
        }
    }
}

// ---------------- launch: fork gemm1+scale onto side stream ----------------
extern "C" void kernel_launch(void* const* d_in, const int* in_sizes, int n_in,
                              void* d_out, int out_size) {
    const float* x   = (const float*)d_in[0];
    const int*   e32 = (const int*)d_in[1];  // int32 or int64 (detected on device)
    const float* W1  = (const float*)d_in[2];
    const float* b1  = (const float*)d_in[3];
    const float* W2  = (const float*)d_in[4];
    const float* b2  = (const float*)d_in[5];
    float* out = (float*)d_out;

    static cudaStream_t s2 = nullptr;
    static cudaEvent_t evFork = nullptr, evDinv = nullptr, evJoin = nullptr;
    if (s2 == nullptr) {
        cudaStreamCreateWithFlags(&s2, cudaStreamNonBlocking);
        cudaEventCreateWithFlags(&evFork, cudaEventDisableTiming);
        cudaEventCreateWithFlags(&evDinv, cudaEventDisableTiming);
        cudaEventCreateWithFlags(&evJoin, cudaEventDisableTiming);
    }

    // Fork: gemm1 (FMA-bound) concurrent with CSR build (memory/atomic-bound).
    cudaEventRecord(evFork, 0);
    cudaStreamWaitEvent(s2, evFork, 0);
    k_gemm1<<<NB_NODES, 256, 0, s2>>>(x, W1);

    k_init<<<NB_NODES, 256>>>(e32);
    k_hist<<<NB_EQUAD, 256>>>(e32);
    k_scanA<<<NB_NODES, 256>>>();          // produces g_dinv
    cudaEventRecord(evDinv, 0);
    cudaStreamWaitEvent(s2, evDinv, 0);
    k_scale<<<NB_NODES, 256, 0, s2>>>();   // h' = dinv * h, overlapped w/ scatter
    cudaEventRecord(evJoin, s2);

    k_scanB<<<1, 512>>>();
    k_scanC<<<NB_NODES, 256>>>();
    k_scatter<<<NB_EPAIR, 256>>>(e32);

    cudaStreamWaitEvent(0, evJoin, 0);
    k_agg1<<<NB_AGG1, 256>>>(b1, W2);
    k_agg2<<<NB_AGG2, 256>>>(b2, out);
}